// round 6
// baseline (speedup 1.0000x reference)
#include <cuda_runtime.h>
#include <cstdint>

#define NN 50000
#define MAXE 1600000

// ---------------- scratch (static device globals; 16B-aligned for float4) --
__device__ __align__(16) float g_tx1[NN * 512];   // 102.4 MB
__device__ __align__(16) float g_tx2[NN * 512];   // 102.4 MB
__device__ __align__(16) float g_h1 [NN * 252];   // padded; only 250 cols used
__device__ __align__(16) float g_h2 [NN * 500];   // 100 MB
__device__ int   g_deg[NN];
__device__ int   g_rowptr[NN + 1];
__device__ int   g_cursor[NN];
__device__ int   g_colidx[MAXE];
__device__ float g_dis[NN];         // deg^{-1/2} (0 for isolated)
__device__ float g_diag[NN];        // 0 for deg>0, -1 for isolated
__device__ int   g_is64;            // 1 if edge_index buffer is int64

// Buffer selector: 0 = external pointer, 1..4 = device scratch buffers.
__device__ __forceinline__ const float* selbuf(int sel, const float* ext) {
    switch (sel) {
        case 1: return g_tx1;
        case 2: return g_tx2;
        case 3: return g_h1;
        case 4: return g_h2;
        default: return ext;
    }
}
__device__ __forceinline__ float* selbuf_mut(int sel, float* ext) {
    switch (sel) {
        case 1: return g_tx1;
        case 2: return g_tx2;
        case 3: return g_h1;
        case 4: return g_h2;
        default: return ext;
    }
}

// Edge accessors robust to int32-vs-int64 storage of edge_index.
__device__ __forceinline__ int edge_at(const void* ei, int E, long long idx) {
    if (g_is64) return (int)((const long long*)ei)[idx];
    return ((const int*)ei)[idx];
}

// ---------------- dtype detection -------------------------------------------
// int64 little-endian node ids < 2^31  =>  every odd int32 word is 0.
__global__ void k_detect(const int* __restrict__ ei32) {
    if (threadIdx.x == 0 && blockIdx.x == 0) {
        int all0 = 1;
        for (int i = 0; i < 64; i++)
            if (ei32[2 * i + 1] != 0) { all0 = 0; break; }
        g_is64 = all0;
    }
}

// ---------------- graph preprocessing --------------------------------------
__global__ void k_zero_deg() {
    int i = blockIdx.x * blockDim.x + threadIdx.x;
    if (i < NN) g_deg[i] = 0;
}

__global__ void k_count(const void* __restrict__ ei, int E) {
    int e = blockIdx.x * blockDim.x + threadIdx.x;
    if (e < E) {
        int dst = edge_at(ei, E, (long long)E + e);   // dst = edge_index[1]
        if ((unsigned)dst < NN) atomicAdd(&g_deg[dst], 1);
    }
}

__global__ void k_dis() {
    int i = blockIdx.x * blockDim.x + threadIdx.x;
    if (i < NN) {
        int d = g_deg[i];
        g_dis[i]  = d > 0 ? rsqrtf((float)d) : 0.0f;
        g_diag[i] = d > 0 ? 0.0f : -1.0f;
    }
}

// single-block exclusive scan of g_deg -> g_rowptr (50001 entries)
__global__ void k_scan() {
    __shared__ int sm[1024];
    __shared__ int carry;
    if (threadIdx.x == 0) { carry = 0; g_rowptr[0] = 0; }
    __syncthreads();
    for (int base = 0; base < NN; base += 1024) {
        int i = base + threadIdx.x;
        int v = (i < NN) ? g_deg[i] : 0;
        sm[threadIdx.x] = v;
        __syncthreads();
        for (int off = 1; off < 1024; off <<= 1) {
            int t = (threadIdx.x >= off) ? sm[threadIdx.x - off] : 0;
            __syncthreads();
            sm[threadIdx.x] += t;
            __syncthreads();
        }
        if (i < NN) g_rowptr[i + 1] = carry + sm[threadIdx.x];
        __syncthreads();
        if (threadIdx.x == 0) carry += sm[1023];
        __syncthreads();
    }
}

__global__ void k_cursor() {
    int i = blockIdx.x * blockDim.x + threadIdx.x;
    if (i < NN) g_cursor[i] = g_rowptr[i];
}

__global__ void k_fill(const void* __restrict__ ei, int E) {
    int e = blockIdx.x * blockDim.x + threadIdx.x;
    if (e < E) {
        int dst = edge_at(ei, E, (long long)E + e);
        int src = edge_at(ei, E, e);
        if ((unsigned)dst < NN && (unsigned)src < NN) {
            int pos = atomicAdd(&g_cursor[dst], 1);
            if ((unsigned)pos < MAXE) g_colidx[pos] = src;
        }
    }
}

// ---------------- SpMM: out = mul*(-dis[i]*sum(dis[s]*hin[s]) + diag[i]*hin[i])
//                        + subcoef * hsub[i]      (warp per dst row, CSR) -----
template <int F>
__global__ void k_spmm(const float* __restrict__ ext, int sel_in, int sel_sub,
                       int sel_out, float mul, float subcoef) {
    constexpr int NR = (F + 31) / 32;
    const float* hin  = selbuf(sel_in, ext);
    const float* hsub = selbuf(sel_sub, ext);
    float* out = selbuf_mut(sel_out, nullptr);

    int warp = (blockIdx.x * blockDim.x + threadIdx.x) >> 5;
    int lane = threadIdx.x & 31;
    if (warp >= NN) return;
    int row = warp;

    int s = g_rowptr[row], e = g_rowptr[row + 1];

    if ((F & 127) == 0) {
        // vectorized path: each lane owns F/128 float4 slots (lane*4 + r*128)
        constexpr int NV = F / 128;
        float4 acc[NV];
#pragma unroll
        for (int r = 0; r < NV; r++) acc[r] = make_float4(0.f, 0.f, 0.f, 0.f);
        for (int j = s; j < e; j++) {
            int src = g_colidx[j];
            float ws = g_dis[src];
            const float4* hp = (const float4*)(hin + (size_t)src * F) + lane;
#pragma unroll
            for (int r = 0; r < NV; r++) {
                float4 v = hp[r * 32];
                acc[r].x += ws * v.x; acc[r].y += ws * v.y;
                acc[r].z += ws * v.z; acc[r].w += ws * v.w;
            }
        }
        float di = g_dis[row], dg = g_diag[row];
        const float4* hr = (const float4*)(hin + (size_t)row * F) + lane;
        const float4* sr = (const float4*)(hsub + (size_t)row * F) + lane;
        float4* orow = (float4*)(out + (size_t)row * F) + lane;
#pragma unroll
        for (int r = 0; r < NV; r++) {
            float4 h = hr[r * 32];
            float4 v;
            v.x = mul * (dg * h.x - di * acc[r].x);
            v.y = mul * (dg * h.y - di * acc[r].y);
            v.z = mul * (dg * h.z - di * acc[r].z);
            v.w = mul * (dg * h.w - di * acc[r].w);
            if (subcoef != 0.0f) {
                float4 sv = sr[r * 32];
                v.x += subcoef * sv.x; v.y += subcoef * sv.y;
                v.z += subcoef * sv.z; v.w += subcoef * sv.w;
            }
            orow[r * 32] = v;
        }
    } else {
        float acc[NR];
#pragma unroll
        for (int r = 0; r < NR; r++) acc[r] = 0.0f;
        for (int j = s; j < e; j++) {
            int src = g_colidx[j];
            float ws = g_dis[src];
            const float* hp = hin + (size_t)src * F;
#pragma unroll
            for (int r = 0; r < NR; r++) {
                int f = lane + r * 32;
                if ((F & 31) == 0 || f < F) acc[r] += ws * hp[f];
            }
        }
        float di = g_dis[row], dg = g_diag[row];
        const float* hr = hin + (size_t)row * F;
        const float* sr = hsub + (size_t)row * F;
        float* orow = out + (size_t)row * F;
#pragma unroll
        for (int r = 0; r < NR; r++) {
            int f = lane + r * 32;
            if ((F & 31) == 0 || f < F) {
                float v = mul * (dg * hr[f] - di * acc[r]);
                if (subcoef != 0.0f) v += subcoef * sr[f];
                orow[f] = v;
            }
        }
    }
}

// ---------------- fused 3-matrix GEMM + bias + relu -------------------------
// C[M,Nout] = relu( [A0|A1|A2] @ W[3K,Nout] + bias ), W already contiguous.
// A1 = g_tx1, A2 = g_tx2 always; A0 selected; C selected.
#define BM 128
#define BN 64
#define BK 16

__global__ void __launch_bounds__(256) k_gemm3(
    const float* __restrict__ extA, int selA0,
    const float* __restrict__ W, const float* __restrict__ bias,
    float* __restrict__ extC, int selC, int M, int K, int Nout) {
    const float* A0 = selbuf(selA0, extA);
    const float* A1 = g_tx1;
    const float* A2 = g_tx2;
    float* C = selbuf_mut(selC, extC);

    __shared__ float As[BK][BM];
    __shared__ float Bs[BK][BN];
    int tid = threadIdx.x;
    int tx = tid & 15;    // 16 col groups * 4 cols
    int ty = tid >> 4;    // 16 row groups * 8 rows
    int blockM = blockIdx.y * BM;
    int blockN = blockIdx.x * BN;
    int Ktot = 3 * K;

    float acc[8][4];
#pragma unroll
    for (int i = 0; i < 8; i++)
#pragma unroll
        for (int j = 0; j < 4; j++) acc[i][j] = 0.0f;

    for (int kt = 0; kt < Ktot; kt += BK) {
        // A tile: 128x16, 8 elems/thread
#pragma unroll
        for (int l = 0; l < 8; l++) {
            int idx = tid + l * 256;
            int r = idx >> 4;
            int c = idx & 15;
            int gr = blockM + r;
            int kk = kt + c;
            float v = 0.0f;
            if (gr < M && kk < Ktot) {
                const float* A = (kk < K) ? A0 : (kk < 2 * K ? A1 : A2);
                int k = (kk < K) ? kk : (kk < 2 * K ? kk - K : kk - 2 * K);
                v = A[(size_t)gr * K + k];
            }
            As[c][r] = v;
        }
        // B tile: 16x64, 4 elems/thread (W flat is exactly [3K, Nout])
#pragma unroll
        for (int l = 0; l < 4; l++) {
            int idx = tid + l * 256;
            int r = idx >> 6;
            int c = idx & 63;
            int kk = kt + r;
            int gc = blockN + c;
            float v = 0.0f;
            if (kk < Ktot && gc < Nout) v = W[(size_t)kk * Nout + gc];
            Bs[r][c] = v;
        }
        __syncthreads();
#pragma unroll
        for (int k = 0; k < BK; k++) {
            float a[8], b[4];
#pragma unroll
            for (int i = 0; i < 8; i++) a[i] = As[k][ty * 8 + i];
#pragma unroll
            for (int j = 0; j < 4; j++) b[j] = Bs[k][tx * 4 + j];
#pragma unroll
            for (int i = 0; i < 8; i++)
#pragma unroll
                for (int j = 0; j < 4; j++) acc[i][j] += a[i] * b[j];
        }
        __syncthreads();
    }

#pragma unroll
    for (int i = 0; i < 8; i++) {
        int gr = blockM + ty * 8 + i;
        if (gr >= M) continue;
#pragma unroll
        for (int j = 0; j < 4; j++) {
            int gc = blockN + tx * 4 + j;
            if (gc < Nout) {
                float v = acc[i][j] + bias[gc];
                C[(size_t)gr * Nout + gc] = v > 0.0f ? v : 0.0f;
            }
        }
    }
}

// ---------------- orchestration ---------------------------------------------
extern "C" void kernel_launch(void* const* d_in, const int* in_sizes, int n_in,
                              void* d_out, int out_size) {
    const float* x  = (const float*)d_in[0];
    const void*  ei = d_in[1];
    const float* w1 = (const float*)d_in[2];
    const float* b1 = (const float*)d_in[3];
    const float* w2 = (const float*)d_in[4];
    const float* b2 = (const float*)d_in[5];
    const float* w3 = (const float*)d_in[6];
    const float* b3 = (const float*)d_in[7];
    float* out = (float*)d_out;
    int E = in_sizes[1] / 2;   // element count of edge_index / 2, either dtype

    int nb = (NN + 255) / 256;
    int eb = (E + 255) / 256;
    k_detect<<<1, 32>>>((const int*)ei);
    k_zero_deg<<<nb, 256>>>();
    k_count<<<eb, 256>>>(ei, E);
    k_dis<<<nb, 256>>>();
    k_scan<<<1, 1024>>>();
    k_cursor<<<nb, 256>>>();
    k_fill<<<eb, 256>>>(ei, E);

    int spb = (NN * 32 + 255) / 256;   // warp per row

    // layer 1: F=512 -> 250   (in: x(ext), out h1)
    k_spmm<512><<<spb, 256>>>(x, 0, 0, 1, 1.0f, 0.0f);   // tx1 = Lhat(x)
    k_spmm<512><<<spb, 256>>>(x, 1, 0, 2, 2.0f, -1.0f);  // tx2 = 2 Lhat(tx1) - x
    {
        dim3 g((250 + BN - 1) / BN, (NN + BM - 1) / BM);
        k_gemm3<<<g, 256>>>(x, 0, w1, b1, nullptr, 3, NN, 512, 250);
    }
    // layer 2: F=250 -> 500   (in: h1, out h2)
    k_spmm<250><<<spb, 256>>>(nullptr, 3, 3, 1, 1.0f, 0.0f);
    k_spmm<250><<<spb, 256>>>(nullptr, 1, 3, 2, 2.0f, -1.0f);
    {
        dim3 g((500 + BN - 1) / BN, (NN + BM - 1) / BM);
        k_gemm3<<<g, 256>>>(nullptr, 3, w2, b2, nullptr, 4, NN, 250, 500);
    }
    // layer 3: F=500 -> 1000  (in: h2, out d_out)
    k_spmm<500><<<spb, 256>>>(nullptr, 4, 4, 1, 1.0f, 0.0f);
    k_spmm<500><<<spb, 256>>>(nullptr, 1, 4, 2, 2.0f, -1.0f);
    {
        dim3 g((1000 + BN - 1) / BN, (NN + BM - 1) / BM);
        k_gemm3<<<g, 256>>>(nullptr, 4, w3, b3, out, 0, NN, 500, 1000);
    }
}

// round 8
// speedup vs baseline: 2.4830x; 2.4830x over previous
#include <cuda_runtime.h>
#include <cuda_bf16.h>
#include <cstdint>

#define NN 50000
#define MAXE 1600000
#define KPADMAX 1536

// ---------------- scratch (static device globals) ---------------------------
__device__ __align__(16) float g_tx1[NN * 512];
__device__ __align__(16) float g_tx2[NN * 512];
__device__ __align__(16) float g_h1 [NN * 252];   // used with stride 250
__device__ __align__(16) float g_h2 [NN * 500];
__device__ __align__(16) __nv_bfloat16 g_Ahi[(size_t)NN * KPADMAX];
__device__ __align__(16) __nv_bfloat16 g_Alo[(size_t)NN * KPADMAX];
__device__ __align__(16) __nv_bfloat16 g_Wthi[1024 * KPADMAX];
__device__ __align__(16) __nv_bfloat16 g_Wtlo[1024 * KPADMAX];
__device__ int   g_deg[NN];
__device__ int   g_rowptr[NN + 1];
__device__ int   g_cursor[NN];
__device__ int   g_colidx[MAXE];
__device__ float g_dis[NN];
__device__ float g_diag[NN];
__device__ int   g_is64;

__device__ __forceinline__ const float* selbuf(int sel, const float* ext) {
    switch (sel) {
        case 1: return g_tx1;
        case 2: return g_tx2;
        case 3: return g_h1;
        case 4: return g_h2;
        default: return ext;
    }
}
__device__ __forceinline__ float* selbuf_mut(int sel, float* ext) {
    switch (sel) {
        case 1: return g_tx1;
        case 2: return g_tx2;
        case 3: return g_h1;
        case 4: return g_h2;
        default: return ext;
    }
}

__device__ __forceinline__ int edge_at(const void* ei, int E, long long idx) {
    if (g_is64) return (int)((const long long*)ei)[idx];
    return ((const int*)ei)[idx];
}

__device__ __forceinline__ uint32_t smem_to_u32(const void* p) {
    uint32_t a;
    asm("{ .reg .u64 t; cvta.to.shared.u64 t, %1; cvt.u32.u64 %0, t; }"
        : "=r"(a) : "l"(p));
    return a;
}

// mma.sync bf16 (sm_80 path; legal on plain sm_103 target)
__device__ __forceinline__ void mma_bf16(float* c, const uint32_t* a, const uint32_t* b) {
    asm volatile("mma.sync.aligned.m16n8k16.row.col.f32.bf16.bf16.f32 "
        "{%0,%1,%2,%3}, {%4,%5,%6,%7}, {%8,%9}, {%0,%1,%2,%3};"
        : "+f"(c[0]), "+f"(c[1]), "+f"(c[2]), "+f"(c[3])
        : "r"(a[0]), "r"(a[1]), "r"(a[2]), "r"(a[3]), "r"(b[0]), "r"(b[1]));
}
__device__ __forceinline__ void ldsm4(uint32_t* r, uint32_t addr) {
    asm volatile("ldmatrix.sync.aligned.m8n8.x4.shared.b16 {%0,%1,%2,%3}, [%4];"
        : "=r"(r[0]), "=r"(r[1]), "=r"(r[2]), "=r"(r[3]) : "r"(addr));
}

// ---------------- dtype detection -------------------------------------------
__global__ void k_detect(const int* __restrict__ ei32) {
    if (threadIdx.x == 0 && blockIdx.x == 0) {
        int all0 = 1;
        for (int i = 0; i < 64; i++)
            if (ei32[2 * i + 1] != 0) { all0 = 0; break; }
        g_is64 = all0;
    }
}

// ---------------- graph preprocessing ---------------------------------------
__global__ void k_zero_deg() {
    int i = blockIdx.x * blockDim.x + threadIdx.x;
    if (i < NN) g_deg[i] = 0;
}
__global__ void k_count(const void* __restrict__ ei, int E) {
    int e = blockIdx.x * blockDim.x + threadIdx.x;
    if (e < E) {
        int dst = edge_at(ei, E, (long long)E + e);
        if ((unsigned)dst < NN) atomicAdd(&g_deg[dst], 1);
    }
}
__global__ void k_dis() {
    int i = blockIdx.x * blockDim.x + threadIdx.x;
    if (i < NN) {
        int d = g_deg[i];
        g_dis[i]  = d > 0 ? rsqrtf((float)d) : 0.0f;
        g_diag[i] = d > 0 ? 0.0f : -1.0f;
    }
}
__global__ void k_scan() {
    __shared__ int sm[1024];
    __shared__ int carry;
    if (threadIdx.x == 0) { carry = 0; g_rowptr[0] = 0; }
    __syncthreads();
    for (int base = 0; base < NN; base += 1024) {
        int i = base + threadIdx.x;
        int v = (i < NN) ? g_deg[i] : 0;
        sm[threadIdx.x] = v;
        __syncthreads();
        for (int off = 1; off < 1024; off <<= 1) {
            int t = (threadIdx.x >= off) ? sm[threadIdx.x - off] : 0;
            __syncthreads();
            sm[threadIdx.x] += t;
            __syncthreads();
        }
        if (i < NN) g_rowptr[i + 1] = carry + sm[threadIdx.x];
        __syncthreads();
        if (threadIdx.x == 0) carry += sm[1023];
        __syncthreads();
    }
}
__global__ void k_cursor() {
    int i = blockIdx.x * blockDim.x + threadIdx.x;
    if (i < NN) g_cursor[i] = g_rowptr[i];
}
__global__ void k_fill(const void* __restrict__ ei, int E) {
    int e = blockIdx.x * blockDim.x + threadIdx.x;
    if (e < E) {
        int dst = edge_at(ei, E, (long long)E + e);
        int src = edge_at(ei, E, e);
        if ((unsigned)dst < NN && (unsigned)src < NN) {
            int pos = atomicAdd(&g_cursor[dst], 1);
            if ((unsigned)pos < MAXE) g_colidx[pos] = src;
        }
    }
}

// ---------------- SpMM (warp per dst row, CSR) ------------------------------
template <int F>
__global__ void k_spmm(const float* __restrict__ ext, int sel_in, int sel_sub,
                       int sel_out, float mul, float subcoef) {
    constexpr int NR = (F + 31) / 32;
    const float* hin  = selbuf(sel_in, ext);
    const float* hsub = selbuf(sel_sub, ext);
    float* out = selbuf_mut(sel_out, nullptr);

    int warp = (blockIdx.x * blockDim.x + threadIdx.x) >> 5;
    int lane = threadIdx.x & 31;
    if (warp >= NN) return;
    int row = warp;
    int s = g_rowptr[row], e = g_rowptr[row + 1];

    if ((F & 127) == 0) {
        constexpr int NV = F / 128;
        float4 acc[NV];
#pragma unroll
        for (int r = 0; r < NV; r++) acc[r] = make_float4(0.f, 0.f, 0.f, 0.f);
        for (int j = s; j < e; j++) {
            int src = g_colidx[j];
            float ws = g_dis[src];
            const float4* hp = (const float4*)(hin + (size_t)src * F) + lane;
#pragma unroll
            for (int r = 0; r < NV; r++) {
                float4 v = hp[r * 32];
                acc[r].x += ws * v.x; acc[r].y += ws * v.y;
                acc[r].z += ws * v.z; acc[r].w += ws * v.w;
            }
        }
        float di = g_dis[row], dg = g_diag[row];
        const float4* hr = (const float4*)(hin + (size_t)row * F) + lane;
        const float4* sr = (const float4*)(hsub + (size_t)row * F) + lane;
        float4* orow = (float4*)(out + (size_t)row * F) + lane;
#pragma unroll
        for (int r = 0; r < NV; r++) {
            float4 h = hr[r * 32];
            float4 v;
            v.x = mul * (dg * h.x - di * acc[r].x);
            v.y = mul * (dg * h.y - di * acc[r].y);
            v.z = mul * (dg * h.z - di * acc[r].z);
            v.w = mul * (dg * h.w - di * acc[r].w);
            if (subcoef != 0.0f) {
                float4 sv = sr[r * 32];
                v.x += subcoef * sv.x; v.y += subcoef * sv.y;
                v.z += subcoef * sv.z; v.w += subcoef * sv.w;
            }
            orow[r * 32] = v;
        }
    } else {
        float acc[NR];
#pragma unroll
        for (int r = 0; r < NR; r++) acc[r] = 0.0f;
        for (int j = s; j < e; j++) {
            int src = g_colidx[j];
            float ws = g_dis[src];
            const float* hp = hin + (size_t)src * F;
#pragma unroll
            for (int r = 0; r < NR; r++) {
                int f = lane + r * 32;
                if ((F & 31) == 0 || f < F) acc[r] += ws * hp[f];
            }
        }
        float di = g_dis[row], dg = g_diag[row];
        const float* hr = hin + (size_t)row * F;
        const float* sr = hsub + (size_t)row * F;
        float* orow = out + (size_t)row * F;
#pragma unroll
        for (int r = 0; r < NR; r++) {
            int f = lane + r * 32;
            if ((F & 31) == 0 || f < F) {
                float v = mul * (dg * hr[f] - di * acc[r]);
                if (subcoef != 0.0f) v += subcoef * sr[f];
                orow[f] = v;
            }
        }
    }
}

// ---------------- bf16 hi/lo conversion kernels ------------------------------
__global__ void k_cvtA(const float* __restrict__ ext, int sel0, int K, int Kpad) {
    long long idx = (long long)blockIdx.x * blockDim.x + threadIdx.x;
    long long total = (long long)NN * Kpad;
    if (idx >= total) return;
    int kk = (int)(idx % Kpad);
    long long m = idx / Kpad;
    float v = 0.0f;
    if (kk < 3 * K) {
        const float* A = (kk < K) ? selbuf(sel0, ext) : (kk < 2 * K ? g_tx1 : g_tx2);
        int k = (kk < K) ? kk : (kk < 2 * K ? kk - K : kk - 2 * K);
        v = A[m * K + k];
    }
    __nv_bfloat16 hi = __float2bfloat16(v);
    __nv_bfloat16 lo = __float2bfloat16(v - __bfloat162float(hi));
    g_Ahi[idx] = hi;
    g_Alo[idx] = lo;
}

__global__ void k_cvtW(const float* __restrict__ W, int K, int N, int Npad, int Kpad) {
    long long idx = (long long)blockIdx.x * blockDim.x + threadIdx.x;
    long long total = (long long)Npad * Kpad;
    if (idx >= total) return;
    int kk = (int)(idx % Kpad);
    int n  = (int)(idx / Kpad);
    float v = (n < N && kk < 3 * K) ? W[(size_t)kk * N + n] : 0.0f;
    __nv_bfloat16 hi = __float2bfloat16(v);
    __nv_bfloat16 lo = __float2bfloat16(v - __bfloat162float(hi));
    g_Wthi[idx] = hi;
    g_Wtlo[idx] = lo;
}

// ---------------- mma.sync GEMM: C = relu(A[M,Kpad] · Wt[Npad,Kpad]^T + bias)
// CTA tile 128x128, BK=32, 8 warps (4 M x 2 N), warp tile 32x64.
// 3-term split: acc += Ahi*Bhi + Ahi*Blo + Alo*Bhi.
#define TBM 128
#define TBN 128
#define TBK 32
#define SROW 40   // padded smem row length in bf16 elements

__global__ void __launch_bounds__(256) k_mmagemm(
    const float* __restrict__ bias, float* __restrict__ extC, int selC,
    int M, int N, int Kpad) {
    __shared__ __align__(16) __nv_bfloat16 sAh[TBM * SROW];
    __shared__ __align__(16) __nv_bfloat16 sAl[TBM * SROW];
    __shared__ __align__(16) __nv_bfloat16 sBh[TBN * SROW];
    __shared__ __align__(16) __nv_bfloat16 sBl[TBN * SROW];

    float* C = selbuf_mut(selC, extC);
    const int tid = threadIdx.x;
    const int wid = tid >> 5, lane = tid & 31;
    const int wm = wid >> 1, wn = wid & 1;     // 4 x 2 warp grid
    const int blockM = blockIdx.y * TBM;
    const int blockN = blockIdx.x * TBN;

    const uint32_t uAh = smem_to_u32(sAh);
    const uint32_t uAl = smem_to_u32(sAl);
    const uint32_t uBh = smem_to_u32(sBh);
    const uint32_t uBl = smem_to_u32(sBl);

    float acc[2][8][4];
#pragma unroll
    for (int i = 0; i < 2; i++)
#pragma unroll
        for (int j = 0; j < 8; j++)
#pragma unroll
            for (int q = 0; q < 4; q++) acc[i][j][q] = 0.0f;

    const int ldrow = tid >> 2;        // 0..63
    const int ldcol = (tid & 3) * 8;   // element offset within 32-col chunk

    for (int kc = 0; kc < Kpad; kc += TBK) {
        // ---- global -> shared: A 128x32 hi/lo, B 128x32 hi/lo
        const uint4 z = make_uint4(0, 0, 0, 0);
#pragma unroll
        for (int p = 0; p < 2; p++) {
            int row = ldrow + p * 64;
            int gA = blockM + row;
            bool okA = gA < M;
            size_t aoff = (size_t)gA * Kpad + kc + ldcol;
            uint4 vh = okA ? *(const uint4*)(g_Ahi + aoff) : z;
            uint4 vl = okA ? *(const uint4*)(g_Alo + aoff) : z;
            *(uint4*)(sAh + row * SROW + ldcol) = vh;
            *(uint4*)(sAl + row * SROW + ldcol) = vl;
            size_t boff = (size_t)(blockN + row) * Kpad + kc + ldcol;
            *(uint4*)(sBh + row * SROW + ldcol) = *(const uint4*)(g_Wthi + boff);
            *(uint4*)(sBl + row * SROW + ldcol) = *(const uint4*)(g_Wtlo + boff);
        }
        __syncthreads();

#pragma unroll
        for (int ks = 0; ks < TBK; ks += 16) {
            // A fragments: 2 mtiles (rows wm*32 + mi*16)
            uint32_t Ah[2][4], Al[2][4];
            {
                int arow = wm * 32 + (lane & 15);
                int akof = ks + ((lane >> 4) * 8);
#pragma unroll
                for (int mi = 0; mi < 2; mi++) {
                    uint32_t off = (uint32_t)((arow + mi * 16) * SROW + akof) * 2;
                    ldsm4(Ah[mi], uAh + off);
                    ldsm4(Al[mi], uAl + off);
                }
            }
            // B fragments: 8 ntiles, 2 per x4 load
            uint32_t Bh[8][2], Bl[8][2];
            {
                int bn = wn * 64 + ((lane >> 4) * 8) + (lane & 7);
                int bk = ks + (((lane >> 3) & 1) * 8);
#pragma unroll
                for (int np = 0; np < 4; np++) {
                    uint32_t off = (uint32_t)((bn + np * 16) * SROW + bk) * 2;
                    uint32_t rh[4], rl[4];
                    ldsm4(rh, uBh + off);
                    ldsm4(rl, uBl + off);
                    Bh[np * 2][0] = rh[0]; Bh[np * 2][1] = rh[1];
                    Bh[np * 2 + 1][0] = rh[2]; Bh[np * 2 + 1][1] = rh[3];
                    Bl[np * 2][0] = rl[0]; Bl[np * 2][1] = rl[1];
                    Bl[np * 2 + 1][0] = rl[2]; Bl[np * 2 + 1][1] = rl[3];
                }
            }
#pragma unroll
            for (int mi = 0; mi < 2; mi++)
#pragma unroll
                for (int ni = 0; ni < 8; ni++) {
                    mma_bf16(acc[mi][ni], Ah[mi], Bh[ni]);
                    mma_bf16(acc[mi][ni], Ah[mi], Bl[ni]);
                    mma_bf16(acc[mi][ni], Al[mi], Bh[ni]);
                }
        }
        __syncthreads();
    }

    // ---- epilogue: bias + relu, guarded store
    const int g = lane >> 2, t = lane & 3;
#pragma unroll
    for (int mi = 0; mi < 2; mi++) {
        int r0 = blockM + wm * 32 + mi * 16 + g;
#pragma unroll
        for (int ni = 0; ni < 8; ni++) {
            int c0 = blockN + wn * 64 + ni * 8 + 2 * t;
            if (c0 < N) {
                bool c1ok = (c0 + 1) < N;
                float bv0 = bias[c0];
                float bv1 = c1ok ? bias[c0 + 1] : 0.0f;
                if (r0 < M) {
                    float v0 = acc[mi][ni][0] + bv0;
                    C[(size_t)r0 * N + c0] = v0 > 0.f ? v0 : 0.f;
                    if (c1ok) {
                        float v1 = acc[mi][ni][1] + bv1;
                        C[(size_t)r0 * N + c0 + 1] = v1 > 0.f ? v1 : 0.f;
                    }
                }
                if (r0 + 8 < M) {
                    float v2 = acc[mi][ni][2] + bv0;
                    C[(size_t)(r0 + 8) * N + c0] = v2 > 0.f ? v2 : 0.f;
                    if (c1ok) {
                        float v3 = acc[mi][ni][3] + bv1;
                        C[(size_t)(r0 + 8) * N + c0 + 1] = v3 > 0.f ? v3 : 0.f;
                    }
                }
            }
        }
    }
}

// ---------------- orchestration ---------------------------------------------
extern "C" void kernel_launch(void* const* d_in, const int* in_sizes, int n_in,
                              void* d_out, int out_size) {
    const float* x  = (const float*)d_in[0];
    const void*  ei = d_in[1];
    const float* w1 = (const float*)d_in[2];
    const float* b1 = (const float*)d_in[3];
    const float* w2 = (const float*)d_in[4];
    const float* b2 = (const float*)d_in[5];
    const float* w3 = (const float*)d_in[6];
    const float* b3 = (const float*)d_in[7];
    float* out = (float*)d_out;
    int E = in_sizes[1] / 2;

    int nb = (NN + 255) / 256;
    int eb = (E + 255) / 256;
    k_detect<<<1, 32>>>((const int*)ei);
    k_zero_deg<<<nb, 256>>>();
    k_count<<<eb, 256>>>(ei, E);
    k_dis<<<nb, 256>>>();
    k_scan<<<1, 1024>>>();
    k_cursor<<<nb, 256>>>();
    k_fill<<<eb, 256>>>(ei, E);

    int spb = (NN * 32 + 255) / 256;
    int mt = (NN + TBM - 1) / TBM;   // 391

    // ---- layer 1: K=512 (Kpad 1536), N=250 (Npad 256), out h1 (sel 3)
    k_spmm<512><<<spb, 256>>>(x, 0, 0, 1, 1.0f, 0.0f);
    k_spmm<512><<<spb, 256>>>(x, 1, 0, 2, 2.0f, -1.0f);
    {
        long long tA = (long long)NN * 1536;
        k_cvtA<<<(unsigned)((tA + 255) / 256), 256>>>(x, 0, 512, 1536);
        long long tW = 256LL * 1536;
        k_cvtW<<<(unsigned)((tW + 255) / 256), 256>>>(w1, 512, 250, 256, 1536);
        dim3 g(256 / TBN, mt);
        k_mmagemm<<<g, 256>>>(b1, nullptr, 3, NN, 250, 1536);
    }
    // ---- layer 2: K=250 (Kpad 768), N=500 (Npad 512), out h2 (sel 4)
    k_spmm<250><<<spb, 256>>>(nullptr, 3, 3, 1, 1.0f, 0.0f);
    k_spmm<250><<<spb, 256>>>(nullptr, 1, 3, 2, 2.0f, -1.0f);
    {
        long long tA = (long long)NN * 768;
        k_cvtA<<<(unsigned)((tA + 255) / 256), 256>>>(nullptr, 3, 250, 768);
        long long tW = 512LL * 768;
        k_cvtW<<<(unsigned)((tW + 255) / 256), 256>>>(w2, 250, 500, 512, 768);
        dim3 g(512 / TBN, mt);
        k_mmagemm<<<g, 256>>>(b2, nullptr, 4, NN, 500, 768);
    }
    // ---- layer 3: K=500 (Kpad 1536), N=1000 (Npad 1024), out d_out
    k_spmm<500><<<spb, 256>>>(nullptr, 4, 4, 1, 1.0f, 0.0f);
    k_spmm<500><<<spb, 256>>>(nullptr, 1, 4, 2, 2.0f, -1.0f);
    {
        long long tA = (long long)NN * 1536;
        k_cvtA<<<(unsigned)((tA + 255) / 256), 256>>>(nullptr, 4, 500, 1536);
        long long tW = 1024LL * 1536;
        k_cvtW<<<(unsigned)((tW + 255) / 256), 256>>>(w3, 500, 1000, 1024, 1536);
        dim3 g(1024 / TBN, mt);
        k_mmagemm<<<g, 256>>>(b3, out, 0, NN, 1000, 1536);
    }
}

// round 9
// speedup vs baseline: 3.0044x; 1.2100x over previous
#include <cuda_runtime.h>
#include <cuda_bf16.h>
#include <cstdint>

#define NN 50000
#define MAXE 1600000
#define KPADMAX 1536

// ---------------- scratch (static device globals) ---------------------------
__device__ __align__(16) float g_tx1[NN * 512];
__device__ __align__(16) float g_tx2[NN * 512];
__device__ __align__(16) float g_h1 [NN * 252];   // used with stride 250
__device__ __align__(16) float g_h2 [NN * 500];
__device__ __align__(16) float g_u  [NN * 768];   // layer-1 GEMM output [u0|u1|u2]
__device__ __align__(16) __nv_bfloat16 g_Ahi[(size_t)NN * KPADMAX];
__device__ __align__(16) __nv_bfloat16 g_Alo[(size_t)NN * KPADMAX];
__device__ __align__(16) __nv_bfloat16 g_Wthi[1024 * KPADMAX];
__device__ __align__(16) __nv_bfloat16 g_Wtlo[1024 * KPADMAX];
__device__ int   g_deg[NN];
__device__ int   g_rowptr[NN + 1];
__device__ int   g_cursor[NN];
__device__ int   g_colidx[MAXE];
__device__ float g_dis[NN];
__device__ float g_diag[NN];
__device__ int   g_is64;

__device__ __forceinline__ const float* selbuf(int sel, const float* ext) {
    switch (sel) {
        case 1: return g_tx1;
        case 2: return g_tx2;
        case 3: return g_h1;
        case 4: return g_h2;
        case 5: return g_u;
        default: return ext;
    }
}
__device__ __forceinline__ float* selbuf_mut(int sel, float* ext) {
    switch (sel) {
        case 1: return g_tx1;
        case 2: return g_tx2;
        case 3: return g_h1;
        case 4: return g_h2;
        case 5: return g_u;
        default: return ext;
    }
}

__device__ __forceinline__ int edge_at(const void* ei, int E, long long idx) {
    if (g_is64) return (int)((const long long*)ei)[idx];
    return ((const int*)ei)[idx];
}

__device__ __forceinline__ uint32_t smem_to_u32(const void* p) {
    uint32_t a;
    asm("{ .reg .u64 t; cvta.to.shared.u64 t, %1; cvt.u32.u64 %0, t; }"
        : "=r"(a) : "l"(p));
    return a;
}

// mma.sync bf16 (sm_80 path; legal on plain sm_103 target)
__device__ __forceinline__ void mma_bf16(float* c, const uint32_t* a, const uint32_t* b) {
    asm volatile("mma.sync.aligned.m16n8k16.row.col.f32.bf16.bf16.f32 "
        "{%0,%1,%2,%3}, {%4,%5,%6,%7}, {%8,%9}, {%0,%1,%2,%3};"
        : "+f"(c[0]), "+f"(c[1]), "+f"(c[2]), "+f"(c[3])
        : "r"(a[0]), "r"(a[1]), "r"(a[2]), "r"(a[3]), "r"(b[0]), "r"(b[1]));
}
__device__ __forceinline__ void ldsm4(uint32_t* r, uint32_t addr) {
    asm volatile("ldmatrix.sync.aligned.m8n8.x4.shared.b16 {%0,%1,%2,%3}, [%4];"
        : "=r"(r[0]), "=r"(r[1]), "=r"(r[2]), "=r"(r[3]) : "r"(addr));
}
__device__ __forceinline__ void cp16(uint32_t dst, const void* src, int src_bytes) {
    asm volatile("cp.async.cg.shared.global [%0], [%1], 16, %2;"
                 :: "r"(dst), "l"(src), "r"(src_bytes));
}
#define CP_COMMIT() asm volatile("cp.async.commit_group;" ::: "memory")
#define CP_WAIT1()  asm volatile("cp.async.wait_group 1;" ::: "memory")
#define CP_WAIT0()  asm volatile("cp.async.wait_group 0;" ::: "memory")

// ---------------- dtype detection -------------------------------------------
__global__ void k_detect(const int* __restrict__ ei32) {
    if (threadIdx.x == 0 && blockIdx.x == 0) {
        int all0 = 1;
        for (int i = 0; i < 64; i++)
            if (ei32[2 * i + 1] != 0) { all0 = 0; break; }
        g_is64 = all0;
    }
}

// ---------------- graph preprocessing ---------------------------------------
__global__ void k_zero_deg() {
    int i = blockIdx.x * blockDim.x + threadIdx.x;
    if (i < NN) g_deg[i] = 0;
}
__global__ void k_count(const void* __restrict__ ei, int E) {
    int e = blockIdx.x * blockDim.x + threadIdx.x;
    if (e < E) {
        int dst = edge_at(ei, E, (long long)E + e);
        if ((unsigned)dst < NN) atomicAdd(&g_deg[dst], 1);
    }
}
__global__ void k_dis() {
    int i = blockIdx.x * blockDim.x + threadIdx.x;
    if (i < NN) {
        int d = g_deg[i];
        g_dis[i]  = d > 0 ? rsqrtf((float)d) : 0.0f;
        g_diag[i] = d > 0 ? 0.0f : -1.0f;
    }
}
__global__ void k_scan() {
    __shared__ int sm[1024];
    __shared__ int carry;
    if (threadIdx.x == 0) { carry = 0; g_rowptr[0] = 0; }
    __syncthreads();
    for (int base = 0; base < NN; base += 1024) {
        int i = base + threadIdx.x;
        int v = (i < NN) ? g_deg[i] : 0;
        sm[threadIdx.x] = v;
        __syncthreads();
        for (int off = 1; off < 1024; off <<= 1) {
            int t = (threadIdx.x >= off) ? sm[threadIdx.x - off] : 0;
            __syncthreads();
            sm[threadIdx.x] += t;
            __syncthreads();
        }
        if (i < NN) g_rowptr[i + 1] = carry + sm[threadIdx.x];
        __syncthreads();
        if (threadIdx.x == 0) carry += sm[1023];
        __syncthreads();
    }
}
__global__ void k_cursor() {
    int i = blockIdx.x * blockDim.x + threadIdx.x;
    if (i < NN) g_cursor[i] = g_rowptr[i];
}
__global__ void k_fill(const void* __restrict__ ei, int E) {
    int e = blockIdx.x * blockDim.x + threadIdx.x;
    if (e < E) {
        int dst = edge_at(ei, E, (long long)E + e);
        int src = edge_at(ei, E, e);
        if ((unsigned)dst < NN && (unsigned)src < NN) {
            int pos = atomicAdd(&g_cursor[dst], 1);
            if ((unsigned)pos < MAXE) g_colidx[pos] = src;
        }
    }
}

// ---------------- SpMM (warp per dst row, CSR; float2 lanes) ----------------
// out[row] = mul*(diag[row]*in[row] - dis[row]*sum(dis[s]*in[s])) +
//            subcoef*sub[row] (+bias, relu).  All widths even.
template <int F>
__global__ void k_spmm2(const float* __restrict__ ext,
                        int sel_in, int off_in, int str_in,
                        int sel_sub, int off_sub, int str_sub,
                        int sel_out, int str_out,
                        float mul, float subcoef,
                        const float* __restrict__ bias, int do_relu) {
    constexpr int NH = F / 2;
    constexpr int NR = (NH + 31) / 32;
    const float* hin  = selbuf(sel_in, ext) + off_in;
    const float* hsub = selbuf(sel_sub, ext) + off_sub;
    float* out = selbuf_mut(sel_out, nullptr);

    int warp = (blockIdx.x * blockDim.x + threadIdx.x) >> 5;
    int lane = threadIdx.x & 31;
    if (warp >= NN) return;
    int row = warp;
    int s = g_rowptr[row], e = g_rowptr[row + 1];

    float2 acc[NR];
#pragma unroll
    for (int r = 0; r < NR; r++) acc[r] = make_float2(0.f, 0.f);

    for (int j = s; j < e; j++) {
        int src = g_colidx[j];
        float ws = g_dis[src];
        const float2* hp = (const float2*)(hin + (size_t)src * str_in);
#pragma unroll
        for (int r = 0; r < NR; r++) {
            int f2 = lane + r * 32;
            if ((NH & 31) == 0 || f2 < NH) {
                float2 v = hp[f2];
                acc[r].x += ws * v.x;
                acc[r].y += ws * v.y;
            }
        }
    }

    float di = g_dis[row], dg = g_diag[row];
    const float2* hr = (const float2*)(hin + (size_t)row * str_in);
    const float2* sr = (const float2*)(hsub + (size_t)row * str_sub);
    float2* orow = (float2*)(out + (size_t)row * str_out);
#pragma unroll
    for (int r = 0; r < NR; r++) {
        int f2 = lane + r * 32;
        if ((NH & 31) == 0 || f2 < NH) {
            float2 h = hr[f2];
            float vx = mul * (dg * h.x - di * acc[r].x);
            float vy = mul * (dg * h.y - di * acc[r].y);
            if (subcoef != 0.0f) {
                float2 sv = sr[f2];
                vx += subcoef * sv.x;
                vy += subcoef * sv.y;
            }
            if (bias) {
                vx += bias[2 * f2];
                vy += bias[2 * f2 + 1];
            }
            if (do_relu) {
                vx = vx > 0.f ? vx : 0.f;
                vy = vy > 0.f ? vy : 0.f;
            }
            orow[f2] = make_float2(vx, vy);
        }
    }
}

// ---------------- bf16 hi/lo conversion kernels ------------------------------
// A = [A0|A1|A2] fp32 (each [NN,K]) -> hi/lo [NN,Kpad]; if Kpad==K only A0.
__global__ void k_cvtA(const float* __restrict__ ext, int sel0, int K, int Kpad) {
    long long idx = (long long)blockIdx.x * blockDim.x + threadIdx.x;
    long long total = (long long)NN * Kpad;
    if (idx >= total) return;
    int kk = (int)(idx % Kpad);
    long long m = idx / Kpad;
    float v = 0.0f;
    if (kk < 3 * K) {
        const float* A = (kk < K) ? selbuf(sel0, ext) : (kk < 2 * K ? g_tx1 : g_tx2);
        int k = (kk < K) ? kk : (kk < 2 * K ? kk - K : kk - 2 * K);
        v = A[m * K + k];
    }
    __nv_bfloat16 hi = __float2bfloat16(v);
    __nv_bfloat16 lo = __float2bfloat16(v - __bfloat162float(hi));
    g_Ahi[idx] = hi;
    g_Alo[idx] = lo;
}

// W fp32 [3K, N] -> transposed hi/lo [Npad, Kpad], zero-padded.
__global__ void k_cvtW(const float* __restrict__ W, int K, int N, int Npad, int Kpad) {
    long long idx = (long long)blockIdx.x * blockDim.x + threadIdx.x;
    long long total = (long long)Npad * Kpad;
    if (idx >= total) return;
    int kk = (int)(idx % Kpad);
    int n  = (int)(idx / Kpad);
    float v = (n < N && kk < 3 * K) ? W[(size_t)kk * N + n] : 0.0f;
    __nv_bfloat16 hi = __float2bfloat16(v);
    __nv_bfloat16 lo = __float2bfloat16(v - __bfloat162float(hi));
    g_Wthi[idx] = hi;
    g_Wtlo[idx] = lo;
}

// Layer-1 combined weights: rows n in [0,768): block b=n>>8, nn=n&255.
// b0: W0-W2, b1: W1, b2: W2  (w1 layout [3,512,250]); cols k in [0,512).
__global__ void k_cvtW1(const float* __restrict__ w) {
    long long idx = (long long)blockIdx.x * blockDim.x + threadIdx.x;
    if (idx >= 768LL * 512) return;
    int k = (int)(idx & 511);
    int n = (int)(idx >> 9);
    int b = n >> 8, nn = n & 255;
    float v = 0.0f;
    if (nn < 250) {
        if (b == 0)
            v = w[(size_t)k * 250 + nn] - w[2 * 512 * 250 + (size_t)k * 250 + nn];
        else
            v = w[(size_t)b * 512 * 250 + (size_t)k * 250 + nn];
    }
    __nv_bfloat16 hi = __float2bfloat16(v);
    __nv_bfloat16 lo = __float2bfloat16(v - __bfloat162float(hi));
    g_Wthi[idx] = hi;
    g_Wtlo[idx] = lo;
}

// ---------------- mma.sync GEMM, cp.async double-buffered --------------------
// C = [A · Wt^T] (+bias, relu if bias != nullptr).
// CTA tile 128x128, BK=32, 8 warps (4x2), warp tile 32x64.
// 3-term split: acc += Ahi*Bhi + Ahi*Blo + Alo*Bhi.
#define TBM 128
#define TBN 128
#define TBK 32
#define SROW 40
#define OFF_AH 0
#define OFF_AL (TBM * SROW * 2)
#define OFF_BH (2 * TBM * SROW * 2)
#define OFF_BL (2 * TBM * SROW * 2 + TBN * SROW * 2)
#define STAGE_BYTES (2 * (TBM + TBN) * SROW * 2)   // 40960
#define SMEM_TOTAL (2 * STAGE_BYTES)               // 81920

__global__ void __launch_bounds__(256) k_mmagemm(
    const float* __restrict__ bias, float* __restrict__ extC, int selC,
    int M, int N, int Kpad) {
    extern __shared__ __align__(16) char dynsm[];
    const uint32_t sbase = smem_to_u32(dynsm);

    float* C = selbuf_mut(selC, extC);
    const int tid = threadIdx.x;
    const int wid = tid >> 5, lane = tid & 31;
    const int wm = wid >> 1, wn = wid & 1;
    const int blockM = blockIdx.y * TBM;
    const int blockN = blockIdx.x * TBN;

    const int ldrow = tid >> 2;
    const int ldcol = (tid & 3) * 8;
    const int nch = Kpad / TBK;

    // prefetch lambda (macro-style)
    auto prefetch = [&](int kc, int st) {
        uint32_t sb = sbase + st * STAGE_BYTES;
#pragma unroll
        for (int p = 0; p < 2; p++) {
            int row = ldrow + p * 64;
            uint32_t dsto = (uint32_t)(row * SROW + ldcol) * 2;
            int gA = blockM + row;
            int okA = (gA < M) ? 16 : 0;
            size_t aoff = (size_t)gA * Kpad + kc * TBK + ldcol;
            cp16(sb + OFF_AH + dsto, g_Ahi + aoff, okA);
            cp16(sb + OFF_AL + dsto, g_Alo + aoff, okA);
            size_t boff = (size_t)(blockN + row) * Kpad + kc * TBK + ldcol;
            cp16(sb + OFF_BH + dsto, g_Wthi + boff, 16);
            cp16(sb + OFF_BL + dsto, g_Wtlo + boff, 16);
        }
    };

    float acc[2][8][4];
#pragma unroll
    for (int i = 0; i < 2; i++)
#pragma unroll
        for (int j = 0; j < 8; j++)
#pragma unroll
            for (int q = 0; q < 4; q++) acc[i][j][q] = 0.0f;

    prefetch(0, 0);
    CP_COMMIT();

    for (int kc = 0; kc < nch; kc++) {
        int st = kc & 1;
        if (kc + 1 < nch) {
            prefetch(kc + 1, st ^ 1);
            CP_COMMIT();
            CP_WAIT1();
        } else {
            CP_WAIT0();
        }
        __syncthreads();

        uint32_t sb = sbase + st * STAGE_BYTES;
        uint32_t uAh = sb + OFF_AH, uAl = sb + OFF_AL;
        uint32_t uBh = sb + OFF_BH, uBl = sb + OFF_BL;

#pragma unroll
        for (int ks = 0; ks < TBK; ks += 16) {
            uint32_t Ah[2][4], Al[2][4];
            {
                int arow = wm * 32 + (lane & 15);
                int akof = ks + ((lane >> 4) * 8);
#pragma unroll
                for (int mi = 0; mi < 2; mi++) {
                    uint32_t off = (uint32_t)((arow + mi * 16) * SROW + akof) * 2;
                    ldsm4(Ah[mi], uAh + off);
                    ldsm4(Al[mi], uAl + off);
                }
            }
            uint32_t Bh[8][2], Bl[8][2];
            {
                int bn = wn * 64 + ((lane >> 4) * 8) + (lane & 7);
                int bk = ks + (((lane >> 3) & 1) * 8);
#pragma unroll
                for (int np = 0; np < 4; np++) {
                    uint32_t off = (uint32_t)((bn + np * 16) * SROW + bk) * 2;
                    uint32_t rh[4], rl[4];
                    ldsm4(rh, uBh + off);
                    ldsm4(rl, uBl + off);
                    Bh[np * 2][0] = rh[0]; Bh[np * 2][1] = rh[1];
                    Bh[np * 2 + 1][0] = rh[2]; Bh[np * 2 + 1][1] = rh[3];
                    Bl[np * 2][0] = rl[0]; Bl[np * 2][1] = rl[1];
                    Bl[np * 2 + 1][0] = rl[2]; Bl[np * 2 + 1][1] = rl[3];
                }
            }
#pragma unroll
            for (int mi = 0; mi < 2; mi++)
#pragma unroll
                for (int ni = 0; ni < 8; ni++) {
                    mma_bf16(acc[mi][ni], Ah[mi], Bh[ni]);
                    mma_bf16(acc[mi][ni], Ah[mi], Bl[ni]);
                    mma_bf16(acc[mi][ni], Al[mi], Bh[ni]);
                }
        }
        __syncthreads();
    }

    // ---- epilogue
    const int g = lane >> 2, t = lane & 3;
#pragma unroll
    for (int mi = 0; mi < 2; mi++) {
        int r0 = blockM + wm * 32 + mi * 16 + g;
#pragma unroll
        for (int ni = 0; ni < 8; ni++) {
            int c0 = blockN + wn * 64 + ni * 8 + 2 * t;
            if (c0 < N) {
                bool c1ok = (c0 + 1) < N;
                float bv0 = bias ? bias[c0] : 0.0f;
                float bv1 = (bias && c1ok) ? bias[c0 + 1] : 0.0f;
                if (r0 < M) {
                    float v0 = acc[mi][ni][0] + bv0;
                    if (bias) v0 = v0 > 0.f ? v0 : 0.f;
                    C[(size_t)r0 * N + c0] = v0;
                    if (c1ok) {
                        float v1 = acc[mi][ni][1] + bv1;
                        if (bias) v1 = v1 > 0.f ? v1 : 0.f;
                        C[(size_t)r0 * N + c0 + 1] = v1;
                    }
                }
                if (r0 + 8 < M) {
                    float v2 = acc[mi][ni][2] + bv0;
                    if (bias) v2 = v2 > 0.f ? v2 : 0.f;
                    C[(size_t)(r0 + 8) * N + c0] = v2;
                    if (c1ok) {
                        float v3 = acc[mi][ni][3] + bv1;
                        if (bias) v3 = v3 > 0.f ? v3 : 0.f;
                        C[(size_t)(r0 + 8) * N + c0 + 1] = v3;
                    }
                }
            }
        }
    }
}

// ---------------- orchestration ---------------------------------------------
extern "C" void kernel_launch(void* const* d_in, const int* in_sizes, int n_in,
                              void* d_out, int out_size) {
    const float* x  = (const float*)d_in[0];
    const void*  ei = d_in[1];
    const float* w1 = (const float*)d_in[2];
    const float* b1 = (const float*)d_in[3];
    const float* w2 = (const float*)d_in[4];
    const float* b2 = (const float*)d_in[5];
    const float* w3 = (const float*)d_in[6];
    const float* b3 = (const float*)d_in[7];
    float* out = (float*)d_out;
    int E = in_sizes[1] / 2;

    cudaFuncSetAttribute(k_mmagemm, cudaFuncAttributeMaxDynamicSharedMemorySize,
                         SMEM_TOTAL);

    int nb = (NN + 255) / 256;
    int eb = (E + 255) / 256;
    k_detect<<<1, 32>>>((const int*)ei);
    k_zero_deg<<<nb, 256>>>();
    k_count<<<eb, 256>>>(ei, E);
    k_dis<<<nb, 256>>>();
    k_scan<<<1, 1024>>>();
    k_cursor<<<nb, 256>>>();
    k_fill<<<eb, 256>>>(ei, E);

    int spb = (NN * 32 + 255) / 256;
    int mt = (NN + TBM - 1) / TBM;   // 391

    // ==== layer 1 (restructured: GEMM first, SpMM on width 250) ====
    // U = x @ [W0-W2 | W1 | W2]^T   -> g_u [NN, 768] raw
    {
        long long tA = (long long)NN * 512;
        k_cvtA<<<(unsigned)((tA + 255) / 256), 256>>>(x, 0, 512, 512);
        k_cvtW1<<<(unsigned)((768LL * 512 + 255) / 256), 256>>>(w1);
        dim3 g(768 / TBN, mt);
        k_mmagemm<<<g, 256, SMEM_TOTAL>>>(nullptr, nullptr, 5, NN, 768, 512);
    }
    // v = u1 + 2*Lhat(u2)          (tx1, width 250)
    k_spmm2<250><<<spb, 256>>>(nullptr, 5, 512, 768, 5, 256, 768, 1, 250,
                               2.0f, 1.0f, nullptr, 0);
    // h1 = relu(u0 + Lhat(v) + b1) (g_h1, width 250)
    k_spmm2<250><<<spb, 256>>>(nullptr, 1, 0, 250, 5, 0, 768, 3, 250,
                               1.0f, 1.0f, b1, 1);

    // ==== layer 2: K=250 (Kpad 768), N=500 (Npad 512), out h2 ====
    k_spmm2<250><<<spb, 256>>>(nullptr, 3, 0, 250, 3, 0, 250, 1, 250,
                               1.0f, 0.0f, nullptr, 0);
    k_spmm2<250><<<spb, 256>>>(nullptr, 1, 0, 250, 3, 0, 250, 2, 250,
                               2.0f, -1.0f, nullptr, 0);
    {
        long long tA = (long long)NN * 768;
        k_cvtA<<<(unsigned)((tA + 255) / 256), 256>>>(nullptr, 3, 250, 768);
        long long tW = 512LL * 768;
        k_cvtW<<<(unsigned)((tW + 255) / 256), 256>>>(w2, 250, 500, 512, 768);
        dim3 g(512 / TBN, mt);
        k_mmagemm<<<g, 256, SMEM_TOTAL>>>(b2, nullptr, 4, NN, 500, 768);
    }

    // ==== layer 3: K=500 (Kpad 1536), N=1000 (Npad 1024), out d_out ====
    k_spmm2<500><<<spb, 256>>>(nullptr, 4, 0, 500, 4, 0, 500, 1, 500,
                               1.0f, 0.0f, nullptr, 0);
    k_spmm2<500><<<spb, 256>>>(nullptr, 1, 0, 500, 4, 0, 500, 2, 500,
                               2.0f, -1.0f, nullptr, 0);
    {
        long long tA = (long long)NN * 1536;
        k_cvtA<<<(unsigned)((tA + 255) / 256), 256>>>(nullptr, 4, 500, 1536);
        long long tW = 1024LL * 1536;
        k_cvtW<<<(unsigned)((tW + 255) / 256), 256>>>(w3, 500, 1000, 1024, 1536);
        dim3 g(1024 / TBN, mt);
        k_mmagemm<<<g, 256, SMEM_TOTAL>>>(b3, out, 0, NN, 1000, 1536);
    }
}